// round 6
// baseline (speedup 1.0000x reference)
#include <cuda_runtime.h>
#include <cuda_fp16.h>
#include <mma.h>

using namespace nvcuda;

#define NN 30000
#define DD 32
#define HH 128
#define KK 10

#define TILES_M  469          // ceil(NN/64)
#define CBLOCKS  157          // compute blocks; each handles 3 tiles

// Scratch (allocation-free rule: __device__ globals)
__device__ __half g_buf[NN * HH];   // g = feature @ W2 in fp16, 7.68 MB
__device__ float  g_va[HH];
__device__ float  g_vc[HH];
__device__ float  g_bias[HH];

// ---------------------------------------------------------------------------
// g = feature @ W2 via wmma (fp16 in, fp32 accum, fp16 store).
// Persistent: 157 blocks, grid-stride over 469 BM=64 tiles (3 each).
// B (W2) loaded ONCE per block into 32KB fp16 smem -> no syncs inside K loop.
// Warp w: warpM = w&3 (16 rows), warpN = w>>2 (64 cols) -> 1x4 acc frags.
// Epilogue: fp32 staging through the 16KB A buffer, two warp-group rounds.
// Block idx CBLOCKS does the tiny precompute instead.
// ---------------------------------------------------------------------------
__global__ __launch_bounds__(256) void gemm_kernel(const float* __restrict__ A,
                                                   const float* __restrict__ B,
                                                   const float* __restrict__ Wt3,
                                                   const float* __restrict__ Wt4,
                                                   const float* __restrict__ b0,
                                                   const float* __restrict__ b1,
                                                   const float* __restrict__ b2) {
    const int tid = threadIdx.x;

    if (blockIdx.x == CBLOCKS) {      // precompute block
        if (tid < HH) {
            int j = tid;
            float va = 0.f, vc = 0.f;
#pragma unroll 8
            for (int h = 0; h < HH; h++) {
                float t  = Wt4[h];
                float w3 = Wt3[h * HH + j];
                va += fmaxf(t, 0.f) * w3;
                vc += fminf(t, 0.f) * w3;
            }
            g_va[j]   = va;
            g_vc[j]   = vc;
            g_bias[j] = b0[j] + b1[j] + b2[j];
        }
        return;
    }

    __shared__ __half Bsh[128 * 128];   // 32KB, [k][n], ld=128
    __shared__ __half Ash[64 * 128];    // 16KB, [m][k], ld=128 (reused as fp32 staging)

    const int wid   = tid >> 5;
    const int lane  = tid & 31;
    const int warpM = wid & 3;          // 16-row slab
    const int warpN = wid >> 2;         // 64-col slab

    // Load all of B once: 128x128 fp32 -> fp16. 4096 float4, 16/thread.
#pragma unroll
    for (int i = 0; i < 16; i++) {
        int f = tid + i * 256;
        int r = f >> 5;
        int q = f & 31;
        float4 v = *reinterpret_cast<const float4*>(&B[r * HH + q * 4]);
        __half h[4] = {__float2half_rn(v.x), __float2half_rn(v.y),
                       __float2half_rn(v.z), __float2half_rn(v.w)};
        *reinterpret_cast<uint2*>(&Bsh[r * 128 + q * 4]) = *reinterpret_cast<uint2*>(h);
    }
    __syncthreads();

    for (int t = blockIdx.x; t < TILES_M; t += CBLOCKS) {
        const int row0 = t * 64;

        // Load A tile: 64x128 fp32 -> fp16. 2048 float4, 8/thread.
#pragma unroll
        for (int i = 0; i < 8; i++) {
            int f = tid + i * 256;
            int m = f >> 5;
            int q = f & 31;
            int row = row0 + m;
            float4 v = make_float4(0.f, 0.f, 0.f, 0.f);
            if (row < NN)
                v = *reinterpret_cast<const float4*>(&A[row * HH + q * 4]);
            __half h[4] = {__float2half_rn(v.x), __float2half_rn(v.y),
                           __float2half_rn(v.z), __float2half_rn(v.w)};
            *reinterpret_cast<uint2*>(&Ash[m * 128 + q * 4]) = *reinterpret_cast<uint2*>(h);
        }
        __syncthreads();

        wmma::fragment<wmma::accumulator, 16, 16, 16, float> acc[4];
#pragma unroll
        for (int nf = 0; nf < 4; nf++) wmma::fill_fragment(acc[nf], 0.f);

#pragma unroll
        for (int k = 0; k < 8; k++) {   // K = 128, no syncs needed
            wmma::fragment<wmma::matrix_a, 16, 16, 16, __half, wmma::row_major> af;
            wmma::load_matrix_sync(af, &Ash[(warpM * 16) * 128 + k * 16], 128);
#pragma unroll
            for (int nf = 0; nf < 4; nf++) {
                wmma::fragment<wmma::matrix_b, 16, 16, 16, __half, wmma::row_major> bf;
                wmma::load_matrix_sync(bf, &Bsh[(k * 16) * 128 + warpN * 64 + nf * 16], 128);
                wmma::mma_sync(acc[nf], af, bf, acc[nf]);
            }
        }
        __syncthreads();   // all warps done reading Ash before staging overwrites it

        // Epilogue: stage fp32 (16x64 = 4KB per warp) through Ash, 4 warps/round.
        float* stage = reinterpret_cast<float*>(Ash);
#pragma unroll
        for (int round = 0; round < 2; round++) {
            if (warpN == round) {
                float* ws = stage + warpM * 1024;
#pragma unroll
                for (int nf = 0; nf < 4; nf++)
                    wmma::store_matrix_sync(ws + nf * 16, acc[nf], 64, wmma::mem_row_major);
                __syncwarp();

                int r     = lane >> 1;             // 16 rows, 2 lanes per row
                int cbase = (lane & 1) * 32;       // 32 cols per lane
                int row   = row0 + warpM * 16 + r;
                if (row < NN) {
                    const float* src_row = ws + r * 64 + cbase;
                    __half h[32];
#pragma unroll
                    for (int j = 0; j < 32; j++) h[j] = __float2half_rn(src_row[j]);
                    uint4* dst = reinterpret_cast<uint4*>(&g_buf[row * HH + warpN * 64 + cbase]);
                    const uint4* hs = reinterpret_cast<const uint4*>(h);
                    dst[0] = hs[0]; dst[1] = hs[1]; dst[2] = hs[2]; dst[3] = hs[3];
                }
            }
            __syncthreads();
        }
    }
}

// ---------------------------------------------------------------------------
// Fused gather + epilogue. 1 warp = 1 node. 2 edges per iteration:
// lanes 0-15 handle edge d (8 fp16 cols each via LDG.128), lanes 16-31 edge
// d+1; cross-half shfl_xor(16) reduction at the end; epilogue on lanes 0-15.
// 256 threads/block = 8 nodes. 30000 % 8 == 0 -> no tail.
// ---------------------------------------------------------------------------
__global__ __launch_bounds__(256) void main_kernel(const float* __restrict__ x,
                                                   const float* __restrict__ label,
                                                   const float* __restrict__ w,
                                                   const float* __restrict__ e_type,
                                                   const int*   __restrict__ src,
                                                   const float* __restrict__ W0,
                                                   const float* __restrict__ W1,
                                                   float* __restrict__ out) {
    const int warp = threadIdx.x >> 5;
    const int lane = threadIdx.x & 31;
    const int n    = blockIdx.x * 8 + warp;

    __shared__ int2 meta[8][DD];   // {src*HH, bits(et)} per edge, 2KB

    // Lane d stages edge d; compute wv for the P/M reduction.
    const int   my_src = src[n * DD + lane];
    const float my_et  = e_type[(n * DD + lane) * 2];
    const float wv     = w[n * DD + lane] * my_et;
    meta[warp][lane] = make_int2(my_src * HH, __float_as_int(my_et));
    __syncwarp();

    // Butterfly-reduce P (relu+ part) and M (relu- part) to all lanes.
    float p = fmaxf(wv, 0.f);
    float m = fminf(wv, 0.f);
#pragma unroll
    for (int o = 16; o > 0; o >>= 1) {
        p += __shfl_xor_sync(0xffffffffu, p, o);
        m += __shfl_xor_sync(0xffffffffu, m, o);
    }

    const int half = lane >> 4;
    const int li   = lane & 15;
    const int c8   = li * 8;      // 8 owned columns

    // Gather: 16 iterations, 2 edges each. 1 LDS.64 + 1 LDG.128 per lane.
    float4 ga = make_float4(0.f, 0.f, 0.f, 0.f);
    float4 gb = make_float4(0.f, 0.f, 0.f, 0.f);
#pragma unroll
    for (int d = 0; d < DD; d += 2) {
        int2  e  = meta[warp][d + half];
        float ed = __int_as_float(e.y);
        uint4 raw = *reinterpret_cast<const uint4*>(&g_buf[e.x + c8]);
        float2 f01 = __half22float2(*reinterpret_cast<__half2*>(&raw.x));
        float2 f23 = __half22float2(*reinterpret_cast<__half2*>(&raw.y));
        float2 f45 = __half22float2(*reinterpret_cast<__half2*>(&raw.z));
        float2 f67 = __half22float2(*reinterpret_cast<__half2*>(&raw.w));
        ga.x = fmaf(ed, f01.x, ga.x);
        ga.y = fmaf(ed, f01.y, ga.y);
        ga.z = fmaf(ed, f23.x, ga.z);
        ga.w = fmaf(ed, f23.y, ga.w);
        gb.x = fmaf(ed, f45.x, gb.x);
        gb.y = fmaf(ed, f45.y, gb.y);
        gb.z = fmaf(ed, f67.x, gb.z);
        gb.w = fmaf(ed, f67.y, gb.w);
    }

    // Cross-half reduction: lane li += lane li+16.
    ga.x += __shfl_xor_sync(0xffffffffu, ga.x, 16);
    ga.y += __shfl_xor_sync(0xffffffffu, ga.y, 16);
    ga.z += __shfl_xor_sync(0xffffffffu, ga.z, 16);
    ga.w += __shfl_xor_sync(0xffffffffu, ga.w, 16);
    gb.x += __shfl_xor_sync(0xffffffffu, gb.x, 16);
    gb.y += __shfl_xor_sync(0xffffffffu, gb.y, 16);
    gb.z += __shfl_xor_sync(0xffffffffu, gb.z, 16);
    gb.w += __shfl_xor_sync(0xffffffffu, gb.w, 16);

    if (half == 0) {
        float4 biasa = *reinterpret_cast<const float4*>(&g_bias[c8]);
        float4 biasb = *reinterpret_cast<const float4*>(&g_bias[c8 + 4]);
        float4 vaa   = *reinterpret_cast<const float4*>(&g_va[c8]);
        float4 vab   = *reinterpret_cast<const float4*>(&g_va[c8 + 4]);
        float4 vca   = *reinterpret_cast<const float4*>(&g_vc[c8]);
        float4 vcb   = *reinterpret_cast<const float4*>(&g_vc[c8 + 4]);

        ga.x += fmaf(p, vaa.x, fmaf(m, vca.x, biasa.x));
        ga.y += fmaf(p, vaa.y, fmaf(m, vca.y, biasa.y));
        ga.z += fmaf(p, vaa.z, fmaf(m, vca.z, biasa.z));
        ga.w += fmaf(p, vaa.w, fmaf(m, vca.w, biasa.w));
        gb.x += fmaf(p, vab.x, fmaf(m, vcb.x, biasb.x));
        gb.y += fmaf(p, vab.y, fmaf(m, vcb.y, biasb.y));
        gb.z += fmaf(p, vab.z, fmaf(m, vcb.z, biasb.z));
        gb.w += fmaf(p, vab.w, fmaf(m, vcb.w, biasb.w));

        const float x0 = x[n * 2 + 0];
        const float x1 = x[n * 2 + 1];
        float4 w0a = *reinterpret_cast<const float4*>(&W0[c8]);
        float4 w0b = *reinterpret_cast<const float4*>(&W0[c8 + 4]);
        float4 w0c = *reinterpret_cast<const float4*>(&W0[HH + c8]);
        float4 w0d = *reinterpret_cast<const float4*>(&W0[HH + c8 + 4]);
        ga.x = fmaf(x0, w0a.x, fmaf(x1, w0c.x, ga.x));
        ga.y = fmaf(x0, w0a.y, fmaf(x1, w0c.y, ga.y));
        ga.z = fmaf(x0, w0a.z, fmaf(x1, w0c.z, ga.z));
        ga.w = fmaf(x0, w0a.w, fmaf(x1, w0c.w, ga.w));
        gb.x = fmaf(x0, w0b.x, fmaf(x1, w0d.x, gb.x));
        gb.y = fmaf(x0, w0b.y, fmaf(x1, w0d.y, gb.y));
        gb.z = fmaf(x0, w0b.z, fmaf(x1, w0d.z, gb.z));
        gb.w = fmaf(x0, w0b.w, fmaf(x1, w0d.w, gb.w));

#pragma unroll
        for (int k = 0; k < KK; k++) {
            float lk = label[n * KK + k];
            float4 w1a = *reinterpret_cast<const float4*>(&W1[k * HH + c8]);
            float4 w1b = *reinterpret_cast<const float4*>(&W1[k * HH + c8 + 4]);
            ga.x = fmaf(lk, w1a.x, ga.x);
            ga.y = fmaf(lk, w1a.y, ga.y);
            ga.z = fmaf(lk, w1a.z, ga.z);
            ga.w = fmaf(lk, w1a.w, ga.w);
            gb.x = fmaf(lk, w1b.x, gb.x);
            gb.y = fmaf(lk, w1b.y, gb.y);
            gb.z = fmaf(lk, w1b.z, gb.z);
            gb.w = fmaf(lk, w1b.w, gb.w);
        }

        float4 ra, rb;
        ra.x = fmaxf(ga.x, 0.f); ra.y = fmaxf(ga.y, 0.f);
        ra.z = fmaxf(ga.z, 0.f); ra.w = fmaxf(ga.w, 0.f);
        rb.x = fmaxf(gb.x, 0.f); rb.y = fmaxf(gb.y, 0.f);
        rb.z = fmaxf(gb.z, 0.f); rb.w = fmaxf(gb.w, 0.f);
        *reinterpret_cast<float4*>(&out[n * HH + c8])     = ra;
        *reinterpret_cast<float4*>(&out[n * HH + c8 + 4]) = rb;
    }
}

// ---------------------------------------------------------------------------
// kernel_launch
// metadata order: 0 feature, 1 x, 2 label, 3 w, 4 e_type, 5 src,
//                 6 W0, 7 b0, 8 W1, 9 b1, 10 W2, 11 b2, 12 Wt3, 13 Wt4
// ---------------------------------------------------------------------------
extern "C" void kernel_launch(void* const* d_in, const int* in_sizes, int n_in,
                              void* d_out, int out_size) {
    const float* feature = (const float*)d_in[0];
    const float* x       = (const float*)d_in[1];
    const float* label   = (const float*)d_in[2];
    const float* w       = (const float*)d_in[3];
    const float* e_type  = (const float*)d_in[4];
    const int*   src     = (const int*)  d_in[5];
    const float* W0      = (const float*)d_in[6];
    const float* b0      = (const float*)d_in[7];
    const float* W1      = (const float*)d_in[8];
    const float* b1      = (const float*)d_in[9];
    const float* W2      = (const float*)d_in[10];
    const float* b2      = (const float*)d_in[11];
    const float* Wt3     = (const float*)d_in[12];
    const float* Wt4     = (const float*)d_in[13];
    float* out = (float*)d_out;

    gemm_kernel<<<CBLOCKS + 1, 256>>>(feature, W2, Wt3, Wt4, b0, b1, b2);
    main_kernel<<<NN / 8, 256>>>(x, label, w, e_type, src, W0, W1, out);
}